// round 16
// baseline (speedup 1.0000x reference)
#include <cuda_runtime.h>
#include <math_constants.h>

// Problem constants (fixed by the reference)
#define NM   32      // molecules
#define NA   40      // atoms per molecule
#define NSPEC 4
#define FEAT 384     // 4*16 + 10*32
#define RCR  5.2f
#define RCA  3.5f
#define BLK  256     // 8 warps per atom
#define NW   8
#define FULL 0xFFFFFFFFu

__global__ __launch_bounds__(BLK, 8)
void aev_kernel(const int* __restrict__ elem,
                const float* __restrict__ coords,
                float* __restrict__ out)
{
    const int bid  = blockIdx.x;        // m*NA + i
    const int m    = bid / NA;
    const int i    = bid % NA;
    const int tid  = threadIdx.x;
    const int lane = tid & 31;
    const int w    = tid >> 5;

    // Compacted angular geometry (built by warp 0)
    __shared__ float4 s_ag[NA];         // {dx, dy, dz, d}
    __shared__ float2 s_af[NA];         // {fcA, elem-as-float-bits}
    // Radial records grouped by species (built by warp 1)
    __shared__ float2 s_rd[NA];         // {d, fcR}
    __shared__ int    srOff[5];
    __shared__ int    scntA;
    // Warp-private pair records (per 32-pair round)
    __shared__ float4 s_pd[NW][32];
    __shared__ int    s_pidb[NW][32];
    // Angular partials: [warp][pid][lane] (lane stride-1 -> conflict-free)
    __shared__ float  s_part[NW][10][32];

    float* o = out + bid * FEAT;

    // ---- Angular per-lane setup (ALL warps, overlaps prologue) ----
    const int at = lane >> 3;
    const int tt = lane & 7;
    const float shfa = 0.9f + 0.65f * (float)at;
    const float z = (CUDART_PI_F / 16.0f) * (float)(2*tt + 1);
    float sz, cz;
    __sincosf(z, &sz, &cz);

    // ---- Prologue, SPLIT: warp 0 = angular side, warp 1 = radial side ----
    if (w == 0) {
        const float xi = coords[(m*NA + i)*3 + 0];
        const float yi = coords[(m*NA + i)*3 + 1];
        const float zi = coords[(m*NA + i)*3 + 2];

        bool inA0=false, inA1=false;
        float dx0=0,dy0=0,dz0=0,d0=0,fA0=0;
        float dx1=0,dy1=0,dz1=0,d1=0,fA1=0;
        int   e0=0, e1v=0;
        {   // atom a0 = lane
            const float* cj = coords + (m*NA + lane)*3;
            dx0 = cj[0]-xi; dy0 = cj[1]-yi; dz0 = cj[2]-zi;
            d0  = sqrtf(dx0*dx0 + dy0*dy0 + dz0*dz0 + 1e-12f);
            fA0 = 0.5f * __cosf((CUDART_PI_F / RCA) * d0) + 0.5f;
            e0  = elem[m*NA + lane];
            inA0 = (lane != i) && (d0 < RCA);
        }
        if (lane < 8) {   // atom a1 = lane+32
            const int a1 = lane + 32;
            const float* cj = coords + (m*NA + a1)*3;
            dx1 = cj[0]-xi; dy1 = cj[1]-yi; dz1 = cj[2]-zi;
            d1  = sqrtf(dx1*dx1 + dy1*dy1 + dz1*dz1 + 1e-12f);
            fA1 = 0.5f * __cosf((CUDART_PI_F / RCA) * d1) + 0.5f;
            e1v = elem[m*NA + a1];
            inA1 = (a1 != i) && (d1 < RCA);
        }
        const unsigned bA0 = __ballot_sync(FULL, inA0);
        const unsigned bA1 = __ballot_sync(FULL, inA1);
        const unsigned lt  = (1u << lane) - 1u;
        if (inA0) {
            int p = __popc(bA0 & lt);
            s_ag[p] = make_float4(dx0, dy0, dz0, d0);
            s_af[p] = make_float2(fA0, __int_as_float(e0));
        }
        if (inA1) {
            int p = __popc(bA0) + __popc(bA1 & lt);
            s_ag[p] = make_float4(dx1, dy1, dz1, d1);
            s_af[p] = make_float2(fA1, __int_as_float(e1v));
        }
        if (lane == 0) scntA = __popc(bA0) + __popc(bA1);
    } else if (w == 1) {
        const float xi = coords[(m*NA + i)*3 + 0];
        const float yi = coords[(m*NA + i)*3 + 1];
        const float zi = coords[(m*NA + i)*3 + 2];

        bool inR0=false, inR1=false;
        float d0=0, fR0=0, d1=0, fR1=0;
        int   e0=0, e1v=0;
        {   // atom a0 = lane
            const float* cj = coords + (m*NA + lane)*3;
            float dx = cj[0]-xi, dy = cj[1]-yi, dz = cj[2]-zi;
            d0  = sqrtf(dx*dx + dy*dy + dz*dz + 1e-12f);
            fR0 = 0.5f * __cosf((CUDART_PI_F / RCR) * d0) + 0.5f;
            e0  = elem[m*NA + lane];
            inR0 = (lane != i) && (d0 < RCR);
        }
        if (lane < 8) {   // atom a1 = lane+32
            const int a1 = lane + 32;
            const float* cj = coords + (m*NA + a1)*3;
            float dx = cj[0]-xi, dy = cj[1]-yi, dz = cj[2]-zi;
            d1  = sqrtf(dx*dx + dy*dy + dz*dz + 1e-12f);
            fR1 = 0.5f * __cosf((CUDART_PI_F / RCR) * d1) + 0.5f;
            e1v = elem[m*NA + a1];
            inR1 = (a1 != i) && (d1 < RCR);
        }
        const unsigned lt = (1u << lane) - 1u;
        unsigned bs0[NSPEC], bs1[NSPEC];
        #pragma unroll
        for (int s = 0; s < NSPEC; s++) {
            bs0[s] = __ballot_sync(FULL, inR0 && (e0  == s));
            bs1[s] = __ballot_sync(FULL, inR1 && (e1v == s));
        }
        int off[NSPEC + 1];
        off[0] = 0;
        #pragma unroll
        for (int s = 0; s < NSPEC; s++)
            off[s+1] = off[s] + __popc(bs0[s]) + __popc(bs1[s]);
        if (inR0) {
            int p = off[e0] + __popc(bs0[e0] & lt);
            s_rd[p] = make_float2(d0, fR0);
        }
        if (inR1) {
            int p = off[e1v] + __popc(bs0[e1v]) + __popc(bs1[e1v] & lt);
            s_rd[p] = make_float2(d1, fR1);
        }
        if (lane < 5) srOff[lane] = off[lane];
    }
    __syncthreads();

    const int cntA = scntA;
    const int np   = cntA * (cntA - 1) / 2;

    // ---- Radial features (warps 0,1): species-s segment only (~3 iters) ----
    if (w < 2) {
        const int f  = w*32 + lane;
        const int s  = f >> 4;
        const int fr = f & 15;
        const float shf = 0.9f + 0.26875f * (float)fr;
        const int n0 = srOff[s], n1 = srOff[s+1];
        float racc = 0.0f;
        #pragma unroll 2
        for (int n = n0; n < n1; n++) {
            float2 rd = s_rd[n];
            float dd = rd.x - shf;
            racc += 0.25f * __expf(-16.0f * dd * dd) * rd.y;
        }
        o[f] = racc;
    }

    // ---- Angular: warp w owns global pairs q = w, w+8, w+16, ... ----
    float acc[10];
    #pragma unroll
    for (int q = 0; q < 10; q++) acc[q] = 0.0f;

    const int nloc = (np > w) ? (np - w + NW - 1) / NW : 0;   // ceil((np-w)/8)
    float4* pd   = s_pd[w];
    int*    pidb = s_pidb[w];

    for (int lbase = 0; lbase < nloc; lbase += 32) {
        const int n = min(32, nloc - lbase);
        if (lane < n) {
            const int q = w + NW*(lbase + lane);         // global pair index
            // Closed-form triangular decode: no serial while-loop
            const int r = np - 1 - q;
            const int t = (int)((sqrtf((float)(8*r + 1)) - 1.0f) * 0.5f);
            const int jj = cntA - 2 - t;
            const int kk = cntA - 1 - (r - ((t*(t+1)) >> 1));
            const float4 gj = s_ag[jj], gk = s_ag[kk];
            const float2 fj = s_af[jj], fk = s_af[kk];
            float dot = gj.x*gk.x + gj.y*gk.y + gj.z*gk.z;
            float dj = gj.w, dk = gk.w;
            float c  = 0.95f * __fdividef(dot, dj * dk); // |c| <= 0.95
            float sn = sqrtf(1.0f - c*c);                // sin(acos(c)) >= 0
            pd[lane] = make_float4(c, sn, 0.5f*(dj + dk), fj.x*fk.x);
            int ej = __float_as_int(fj.y), ek = __float_as_int(fk.y);
            int lo = min(ej, ek), hi = max(ej, ek);
            pidb[lane] = lo*NSPEC - (lo*(lo-1))/2 + (hi - lo);
        }
        __syncwarp();
        #pragma unroll 4
        for (int p = 0; p < n; p++) {
            const int    pid = pidb[p];   // warp-uniform broadcast
            const float4 r   = pd[p];     // broadcast LDS.128
            float cth = r.x*cz + r.y*sz;  // cos(theta - z)
            float x   = 0.5f + 0.5f*cth;
            float x2  = x*x;
            float x4  = x2*x2;
            float x8  = x4*x4;
            float x16 = x8*x8;
            float x32 = x16*x16;          // x^ZETA, ZETA=32
            float dr  = r.z - shfa;
            float term = 2.0f * __expf(-8.0f * dr * dr) * x32 * r.w;
            #pragma unroll
            for (int q = 0; q < 10; q++)
                acc[q] += (pid == q) ? term : 0.0f;      // select-add, no branch
        }
        __syncwarp();
    }

    // ---- Write partials, balanced barrier, combine + store ----
    #pragma unroll
    for (int q = 0; q < 10; q++) s_part[w][q][lane] = acc[q];
    __syncthreads();

    // warp w reduces pids {w} and {w+8} (w<2); 8 partials each
    #pragma unroll
    for (int q = w; q < 10; q += NW) {
        float v = 0.0f;
        #pragma unroll
        for (int ww = 0; ww < NW; ww++)
            v += s_part[ww][q][lane];
        o[64 + q*32 + lane] = v;
    }
}

extern "C" void kernel_launch(void* const* d_in, const int* in_sizes, int n_in,
                              void* d_out, int out_size)
{
    const int*   elem   = (const int*)  d_in[0];   // elem_idxs (M*A) int32
    const float* coords = (const float*)d_in[1];   // coords (M*A*3) float32
    float*       out    = (float*)d_out;           // (M*A*FEAT) float32
    (void)in_sizes; (void)n_in; (void)out_size;
    aev_kernel<<<NM * NA, BLK>>>(elem, coords, out);
}